// round 16
// baseline (speedup 1.0000x reference)
#include <cuda_runtime.h>
#include <cuda_fp16.h>
#include <cstdint>
#include <cstddef>

#define NN_ 8192
#define MM_ 4096
#define EE_ 512

// ---------------- scratch (__device__ globals; no allocation) ----------------
__device__ __half g_vcode_h[NN_ * EE_];
__device__ __half g_obs_h  [MM_ * EE_];
__device__ __half g_Wcat   [3 * EE_ * EE_];          // [Wq; Wk; Wv]
__device__ __half g_QKV    [(size_t)NN_ * 3 * EE_];  // cols: Q|Kv|Vv
__device__ __half g_KoVo   [(size_t)MM_ * 2 * EE_];  // cols: Ko|Vo
__device__ __half g_VoT    [EE_ * MM_];              // [E, M]
__device__ __half g_S      [(size_t)NN_ * MM_];      // exp-weights (unnorm)
__device__ float  g_Zpart  [64 * NN_];               // [16 bx][4 wn][row]
__device__ float  g_Opart  [4][(size_t)NN_ * EE_];   // split-K partials

// ------------------------------- PTX helpers -------------------------------
__device__ __forceinline__ uint32_t smem_u32(const void* p) {
    uint32_t a;
    asm("{ .reg .u64 t; cvta.to.shared.u64 t, %1; cvt.u32.u64 %0, t; }"
        : "=r"(a) : "l"(p));
    return a;
}
__device__ __forceinline__ void cp16(uint32_t smem, const void* gmem) {
    asm volatile("cp.async.cg.shared.global [%0], [%1], 16;\n" :: "r"(smem), "l"(gmem));
}
#define CP_COMMIT() asm volatile("cp.async.commit_group;\n" ::: "memory")

__device__ __forceinline__ void ldm_x4(uint32_t& r0, uint32_t& r1,
                                       uint32_t& r2, uint32_t& r3, uint32_t addr) {
    asm volatile("ldmatrix.sync.aligned.m8n8.x4.shared.b16 {%0,%1,%2,%3}, [%4];"
                 : "=r"(r0), "=r"(r1), "=r"(r2), "=r"(r3) : "r"(addr));
}
__device__ __forceinline__ uint32_t swz(uint32_t off) {
    return off ^ ((off >> 3) & 0x70);
}
__device__ __forceinline__ void store_pair(float* p, float x, float y) {
    *(float2*)p = make_float2(x, y);
}
__device__ __forceinline__ void store_pair(__half* p, float x, float y) {
    *(__half2*)p = __floats2half2_rn(x, y);
}

// ---------------------------------------------------------------------------
// fp16-input, f32-acc NT GEMM body: CTA 128x256x64, 512 thr, warp tile 64x32,
// 4-stage cp.async. (Used by proj_gemm and out_gemm.)
// ---------------------------------------------------------------------------
#define GBM 128
#define GBN 256
#define GBK 64
#define GTHREADS 512
#define A_STG 16384
#define B_STG 32768
#define STG_B (A_STG + B_STG)
#define G_SMEM_TOTAL (4 * STG_B)         // 196608

template <typename OutT>
__device__ __forceinline__ void gemm_body_f32(
    const __half* __restrict__ A, const __half* __restrict__ B,
    OutT* __restrict__ C,
    int lda, int ldb, int ldc, int KT, int row0, int col0)
{
    extern __shared__ char smem[];
    const uint32_t sb = smem_u32(smem);

    const int tid  = threadIdx.x;
    const int wid  = tid >> 5, lane = tid & 31;
    const int wm   = (wid >> 3) * 64;
    const int wn   = (wid & 7) * 32;
    const int gID  = lane >> 2;
    const int tID  = lane & 3;

    const int lr = lane & 7;
    const int lm = lane >> 3;
    uint32_t baseA[4], baseB[2];
#pragma unroll
    for (int mi = 0; mi < 4; ++mi)
        baseA[mi] = (uint32_t)(wm + mi * 16 + (lm & 1) * 8 + lr) * 128 + (lm >> 1) * 16;
#pragma unroll
    for (int nj = 0; nj < 2; ++nj)
        baseB[nj] = (uint32_t)(wn + nj * 16 + (lm >> 1) * 8 + lr) * 128 + (lm & 1) * 16;

    auto load_stage = [&](int s, int k0) {
        const uint32_t abase = sb + s * STG_B;
#pragma unroll
        for (int i = 0; i < 2; ++i) {
            int idx = tid + GTHREADS * i;
            int r = idx >> 3, ck = idx & 7;
            cp16(abase + swz(r * 128 + ck * 16),
                 A + (size_t)(row0 + r) * lda + k0 + ck * 8);
        }
        const uint32_t bbase = abase + A_STG;
#pragma unroll
        for (int i = 0; i < 4; ++i) {
            int idx = tid + GTHREADS * i;
            int r = idx >> 3, ck = idx & 7;
            cp16(bbase + swz(r * 128 + ck * 16),
                 B + (size_t)(col0 + r) * ldb + k0 + ck * 8);
        }
        CP_COMMIT();
    };

    float acc[4][4][4];
#pragma unroll
    for (int mi = 0; mi < 4; ++mi)
#pragma unroll
        for (int ni = 0; ni < 4; ++ni)
#pragma unroll
            for (int q = 0; q < 4; ++q) acc[mi][ni][q] = 0.f;

    load_stage(0, 0);
    load_stage(1, GBK);
    load_stage(2, 2 * GBK);

    for (int kt = 0; kt < KT; ++kt) {
        const int s = kt & 3;
        if (kt <= KT - 3)      asm volatile("cp.async.wait_group 2;\n" ::: "memory");
        else if (kt == KT - 2) asm volatile("cp.async.wait_group 1;\n" ::: "memory");
        else                   asm volatile("cp.async.wait_group 0;\n" ::: "memory");
        __syncthreads();
        if (kt + 3 < KT) load_stage((kt + 3) & 3, (kt + 3) * GBK);

        const uint32_t Ab = sb + s * STG_B;
        const uint32_t Bb = Ab + A_STG;
#pragma unroll
        for (int kb = 0; kb < 4; ++kb) {
            const uint32_t ko = kb * 32;
            uint32_t a[4][4], b[2][4];
#pragma unroll
            for (int mi = 0; mi < 4; ++mi)
                ldm_x4(a[mi][0], a[mi][1], a[mi][2], a[mi][3],
                       Ab + swz(baseA[mi] + ko));
#pragma unroll
            for (int nj = 0; nj < 2; ++nj)
                ldm_x4(b[nj][0], b[nj][1], b[nj][2], b[nj][3],
                       Bb + swz(baseB[nj] + ko));
#pragma unroll
            for (int mi = 0; mi < 4; ++mi) {
#pragma unroll
                for (int ni = 0; ni < 4; ++ni) {
                    const uint32_t b0 = b[ni >> 1][(ni & 1) * 2];
                    const uint32_t b1 = b[ni >> 1][(ni & 1) * 2 + 1];
                    asm volatile(
                        "mma.sync.aligned.m16n8k16.row.col.f32.f16.f16.f32 "
                        "{%0,%1,%2,%3}, {%4,%5,%6,%7}, {%8,%9}, {%0,%1,%2,%3};\n"
                        : "+f"(acc[mi][ni][0]), "+f"(acc[mi][ni][1]),
                          "+f"(acc[mi][ni][2]), "+f"(acc[mi][ni][3])
                        : "r"(a[mi][0]), "r"(a[mi][1]), "r"(a[mi][2]), "r"(a[mi][3]),
                          "r"(b0), "r"(b1));
                }
            }
        }
    }

#pragma unroll
    for (int mi = 0; mi < 4; ++mi) {
#pragma unroll
        for (int ni = 0; ni < 4; ++ni) {
            const int r  = row0 + wm + mi * 16 + gID;
            const int cc = col0 + wn + ni * 8 + tID * 2;
            store_pair(C + (size_t)r * ldc + cc,       acc[mi][ni][0], acc[mi][ni][1]);
            store_pair(C + (size_t)(r + 8) * ldc + cc, acc[mi][ni][2], acc[mi][ni][3]);
        }
    }
}

// ---------------------------------------------------------------------------
// Merged projections (f32 acc): bid<384 -> QKV; else -> KoVo
// ---------------------------------------------------------------------------
__global__ __launch_bounds__(GTHREADS, 1) void proj_gemm(
    const __half* __restrict__ vch, const __half* __restrict__ obh,
    const __half* __restrict__ Wcat,
    __half* __restrict__ QKV, __half* __restrict__ KoVo)
{
    const int bid = blockIdx.x;
    if (bid < 384) {
        const int bx = bid % 6, by = bid / 6;
        gemm_body_f32<__half>(vch, Wcat, QKV, EE_, EE_, 1536, EE_ / GBK,
                              by * GBM, bx * GBN);
    } else {
        const int b2 = bid - 384;
        const int bx = b2 % 4, by = b2 / 4;
        gemm_body_f32<__half>(obh, Wcat + EE_ * EE_, KoVo, EE_, EE_, 1024,
                              EE_ / GBK, by * GBM, bx * GBN);
    }
}

// O partials = expS @ VoT^T, split-K=4 via grid.z
__global__ __launch_bounds__(GTHREADS, 1) void out_gemm(
    const __half* __restrict__ S, const __half* __restrict__ VoT,
    float* __restrict__ O)
{
    const int kz = blockIdx.z;
    gemm_body_f32<float>(S + (size_t)kz * (MM_ / 4),
                         VoT + (size_t)kz * (MM_ / 4),
                         O + (size_t)kz * NN_ * EE_,
                         MM_, MM_, EE_, (MM_ / 4) / GBK,
                         blockIdx.y * GBM, blockIdx.x * GBN);
}

// ---------------------------------------------------------------------------
// score GEMM: CTA 256x256x64, 512 thr (16 warps, warp tile 64x64), f16 acc,
// 3-stage cp.async. Epilogue: exp((acc)/T) -> S fp16 + Zpart row sums.
// ---------------------------------------------------------------------------
#define SBM 256
#define SBN 256
#define SBK 64
#define SA_STG 32768                     // 256 rows * 128B
#define S_STG (2 * SA_STG)               // 65536
#define S_SMEM_TOTAL (3 * S_STG)         // 196608

__global__ __launch_bounds__(GTHREADS, 1) void score_gemm(
    const __half* __restrict__ A,        // QKV (Q cols), lda 1536
    const __half* __restrict__ B,        // KoVo (Ko cols), ldb 1024
    __half* __restrict__ S, float* __restrict__ Zpart)
{
    extern __shared__ char smem[];
    const uint32_t sb = smem_u32(smem);

    const int tid  = threadIdx.x;
    const int wid  = tid >> 5, lane = tid & 31;
    const int wm   = (wid >> 2) * 64;   // 0..192
    const int wnI  = wid & 3;
    const int wn   = wnI * 64;          // 0..192
    const int gID  = lane >> 2;
    const int tID  = lane & 3;
    const int row0 = blockIdx.y * SBM;
    const int col0 = blockIdx.x * SBN;
    const int KT   = EE_ / SBK;          // 8
    const int lda = 1536, ldb = 1024;

    const int lr = lane & 7;
    const int lm = lane >> 3;
    uint32_t baseA[4], baseB[4];
#pragma unroll
    for (int mi = 0; mi < 4; ++mi)
        baseA[mi] = (uint32_t)(wm + mi * 16 + (lm & 1) * 8 + lr) * 128 + (lm >> 1) * 16;
#pragma unroll
    for (int nj = 0; nj < 4; ++nj)
        baseB[nj] = (uint32_t)(wn + nj * 16 + (lm >> 1) * 8 + lr) * 128 + (lm & 1) * 16;

    auto load_stage = [&](int s, int k0) {
        const uint32_t abase = sb + s * S_STG;
#pragma unroll
        for (int i = 0; i < 4; ++i) {     // A: 2048 chunks / 512 thr
            int idx = tid + GTHREADS * i;
            int r = idx >> 3, ck = idx & 7;
            cp16(abase + swz(r * 128 + ck * 16),
                 A + (size_t)(row0 + r) * lda + k0 + ck * 8);
        }
        const uint32_t bbase = abase + SA_STG;
#pragma unroll
        for (int i = 0; i < 4; ++i) {     // B: 2048 chunks / 512 thr
            int idx = tid + GTHREADS * i;
            int r = idx >> 3, ck = idx & 7;
            cp16(bbase + swz(r * 128 + ck * 16),
                 B + (size_t)(col0 + r) * ldb + k0 + ck * 8);
        }
        CP_COMMIT();
    };

    // f16 accumulators: [mi][ni] x {c0,c1} packed half2
    uint32_t acc[4][8][2];
#pragma unroll
    for (int mi = 0; mi < 4; ++mi)
#pragma unroll
        for (int ni = 0; ni < 8; ++ni) {
            acc[mi][ni][0] = 0u;
            acc[mi][ni][1] = 0u;
        }

    load_stage(0, 0);
    load_stage(1, SBK);

    for (int kt = 0; kt < KT; ++kt) {
        const int s = kt % 3;
        if (kt <= KT - 2) asm volatile("cp.async.wait_group 1;\n" ::: "memory");
        else              asm volatile("cp.async.wait_group 0;\n" ::: "memory");
        __syncthreads();
        if (kt + 2 < KT) load_stage((kt + 2) % 3, (kt + 2) * SBK);

        const uint32_t Ab = sb + s * S_STG;
        const uint32_t Bb = Ab + SA_STG;
#pragma unroll
        for (int kb = 0; kb < 4; ++kb) {
            const uint32_t ko = kb * 32;
            uint32_t a[4][4], b[4][4];
#pragma unroll
            for (int mi = 0; mi < 4; ++mi)
                ldm_x4(a[mi][0], a[mi][1], a[mi][2], a[mi][3],
                       Ab + swz(baseA[mi] + ko));
#pragma unroll
            for (int nj = 0; nj < 4; ++nj)
                ldm_x4(b[nj][0], b[nj][1], b[nj][2], b[nj][3],
                       Bb + swz(baseB[nj] + ko));
#pragma unroll
            for (int mi = 0; mi < 4; ++mi) {
#pragma unroll
                for (int ni = 0; ni < 8; ++ni) {
                    const uint32_t b0 = b[ni >> 1][(ni & 1) * 2];
                    const uint32_t b1 = b[ni >> 1][(ni & 1) * 2 + 1];
                    asm volatile(
                        "mma.sync.aligned.m16n8k16.row.col.f16.f16.f16.f16 "
                        "{%0,%1}, {%2,%3,%4,%5}, {%6,%7}, {%0,%1};\n"
                        : "+r"(acc[mi][ni][0]), "+r"(acc[mi][ni][1])
                        : "r"(a[mi][0]), "r"(a[mi][1]), "r"(a[mi][2]), "r"(a[mi][3]),
                          "r"(b0), "r"(b1));
                }
            }
        }
    }

    // epilogue: exp((logit)*invT) -> fp16 store + per-warp-slice row sums
    const float invT = 0.044194173824159216f;  // 1/sqrt(512)
    const int zslice = blockIdx.x * 4 + wnI;
#pragma unroll
    for (int mi = 0; mi < 4; ++mi) {
        const int r = row0 + wm + mi * 16 + gID;
        float s0 = 0.f, s1 = 0.f;
#pragma unroll
        for (int ni = 0; ni < 8; ++ni) {
            const int cc = col0 + wn + ni * 8 + tID * 2;
            float2 c0 = __half22float2(*(const __half2*)&acc[mi][ni][0]);
            float2 c1 = __half22float2(*(const __half2*)&acc[mi][ni][1]);
            float e0 = __expf(c0.x * invT);
            float e1 = __expf(c0.y * invT);
            float e2 = __expf(c1.x * invT);
            float e3 = __expf(c1.y * invT);
            s0 += e0 + e1;
            s1 += e2 + e3;
            store_pair(S + (size_t)r * MM_ + cc,       e0, e1);
            store_pair(S + (size_t)(r + 8) * MM_ + cc, e2, e3);
        }
        s0 += __shfl_xor_sync(0xffffffffu, s0, 1);
        s0 += __shfl_xor_sync(0xffffffffu, s0, 2);
        s1 += __shfl_xor_sync(0xffffffffu, s1, 1);
        s1 += __shfl_xor_sync(0xffffffffu, s1, 2);
        if (tID == 0) {
            Zpart[(size_t)zslice * NN_ + r]     = s0;
            Zpart[(size_t)zslice * NN_ + r + 8] = s1;
        }
    }
}

// ---------------------------------------------------------------------------
// Merged float -> fp16 conversion for all 5 inputs, 4 elems/thread
// ---------------------------------------------------------------------------
#define CVT_N_VC (NN_ * EE_ / 4)
#define CVT_N_OB (MM_ * EE_ / 4)
#define CVT_N_W  (EE_ * EE_ / 4)
#define CVT_TOTAL (CVT_N_VC + CVT_N_OB + 3 * CVT_N_W)

__global__ __launch_bounds__(256) void cvt_all(
    const float* __restrict__ v_code, const float* __restrict__ obs_code,
    const float* __restrict__ Wq, const float* __restrict__ Wk,
    const float* __restrict__ Wv,
    __half* __restrict__ vch, __half* __restrict__ obh,
    __half* __restrict__ Wcat)
{
    int i = blockIdx.x * blockDim.x + threadIdx.x;
    if (i >= CVT_TOTAL) return;
    const float* src;
    __half* dst;
    int j = i;
    if (j < CVT_N_VC) { src = v_code; dst = vch; }
    else if ((j -= CVT_N_VC) < CVT_N_OB) { src = obs_code; dst = obh; }
    else if ((j -= CVT_N_OB) < CVT_N_W) { src = Wq; dst = Wcat; }
    else if ((j -= CVT_N_W) < CVT_N_W)  { src = Wk; dst = Wcat + EE_ * EE_; }
    else { j -= CVT_N_W; src = Wv; dst = Wcat + 2 * EE_ * EE_; }
    float4 v = ((const float4*)src)[j];
    ((__half2*)dst)[2 * j]     = __floats2half2_rn(v.x, v.y);
    ((__half2*)dst)[2 * j + 1] = __floats2half2_rn(v.z, v.w);
}

// ---------------------------------------------------------------------------
// Transpose Vo (cols 512..1023 of KoVo [4096, 1024]) -> VoT [512, 4096]
// ---------------------------------------------------------------------------
__global__ __launch_bounds__(256) void transpose_vo(
    const __half* __restrict__ KoVo, __half* __restrict__ VoT)
{
    __shared__ __half t[32][33];
    const int tx = threadIdx.x & 31, ty = threadIdx.x >> 5;
    const int m0 = blockIdx.x * 32;
    const int e0 = blockIdx.y * 32;
#pragma unroll
    for (int p = 0; p < 4; ++p)
        t[ty + p * 8][tx] = KoVo[(size_t)(m0 + ty + p * 8) * 1024 + 512 + e0 + tx];
    __syncthreads();
#pragma unroll
    for (int p = 0; p < 4; ++p)
        VoT[(size_t)(e0 + ty + p * 8) * MM_ + m0 + tx] = t[tx][ty + p * 8];
}

// ---------------------------------------------------------------------------
// Epilogue (fused): sv = Q.Kv diag; Z = sum Zpart(64) + exp(sv/T);
// x = (sum O partials)/Ztot + w0*Vv + v_code;  out = LN(x)*gamma + beta
// ---------------------------------------------------------------------------
__global__ __launch_bounds__(128) void ln_residual(
    const float* __restrict__ Op,        // 4 partial buffers
    const __half* __restrict__ QKV,
    const float* __restrict__ Zpart,
    const float* __restrict__ vcode,
    const float* __restrict__ gamma, const float* __restrict__ beta,
    float* __restrict__ out)
{
    const int row  = blockIdx.x;
    const int tid  = threadIdx.x;
    const int lane = tid & 31, wid = tid >> 5;
    const size_t base = (size_t)row * EE_ + tid * 4;

    uint2 qu  = *(const uint2*)(QKV + (size_t)row * 1536 + tid * 4);
    uint2 ku  = *(const uint2*)(QKV + (size_t)row * 1536 + 512 + tid * 4);
    float2 q01 = __half22float2(*(const __half2*)&qu.x);
    float2 q23 = __half22float2(*(const __half2*)&qu.y);
    float2 k01 = __half22float2(*(const __half2*)&ku.x);
    float2 k23 = __half22float2(*(const __half2*)&ku.y);
    float svp = q01.x * k01.x + q01.y * k01.y + q23.x * k23.x + q23.y * k23.y;
    float zp  = (tid < 64) ? Zpart[(size_t)tid * NN_ + row] : 0.f;

    __shared__ float sA[4], sB[4];
#pragma unroll
    for (int o = 16; o; o >>= 1) {
        svp += __shfl_xor_sync(0xffffffffu, svp, o);
        zp  += __shfl_xor_sync(0xffffffffu, zp, o);
    }
    if (lane == 0) { sA[wid] = svp; sB[wid] = zp; }
    __syncthreads();
    const float sv = sA[0] + sA[1] + sA[2] + sA[3];
    const float Z  = sB[0] + sB[1] + sB[2] + sB[3];

    const float invT = 0.044194173824159216f;
    const float es   = __expf(sv * invT);
    const float invZ = 1.f / (Z + es);
    const float w    = es * invZ;

    float4 o0 = *(const float4*)(Op + base);
    float4 o1 = *(const float4*)(Op + (size_t)NN_ * EE_ + base);
    float4 o2 = *(const float4*)(Op + 2 * (size_t)NN_ * EE_ + base);
    float4 o3 = *(const float4*)(Op + 3 * (size_t)NN_ * EE_ + base);
    float4 os;
    os.x = (o0.x + o1.x) + (o2.x + o3.x);
    os.y = (o0.y + o1.y) + (o2.y + o3.y);
    os.z = (o0.z + o1.z) + (o2.z + o3.z);
    os.w = (o0.w + o1.w) + (o2.w + o3.w);

    uint2 vvu = *(const uint2*)(QKV + (size_t)row * 1536 + 1024 + tid * 4);
    float2 v01 = __half22float2(*(const __half2*)&vvu.x);
    float2 v23 = __half22float2(*(const __half2*)&vvu.y);
    float4 vc = *(const float4*)(vcode + base);
    float4 x;
    x.x = fmaf(w, v01.x, os.x * invZ) + vc.x;
    x.y = fmaf(w, v01.y, os.y * invZ) + vc.y;
    x.z = fmaf(w, v23.x, os.z * invZ) + vc.z;
    x.w = fmaf(w, v23.y, os.w * invZ) + vc.w;

    __shared__ float sred[4];
    float s = x.x + x.y + x.z + x.w;
#pragma unroll
    for (int o2s = 16; o2s; o2s >>= 1) s += __shfl_xor_sync(0xffffffffu, s, o2s);
    if (lane == 0) sred[wid] = s;
    __syncthreads();
    const float mu = (sred[0] + sred[1] + sred[2] + sred[3]) * (1.f / 512.f);

    float4 d;
    d.x = x.x - mu; d.y = x.y - mu; d.z = x.z - mu; d.w = x.w - mu;
    float s2 = d.x * d.x + d.y * d.y + d.z * d.z + d.w * d.w;
#pragma unroll
    for (int o2s = 16; o2s; o2s >>= 1) s2 += __shfl_xor_sync(0xffffffffu, s2, o2s);
    __syncthreads();
    if (lane == 0) sred[wid] = s2;
    __syncthreads();
    const float var = (sred[0] + sred[1] + sred[2] + sred[3]) * (1.f / 512.f);
    const float r = rsqrtf(var + 1e-6f);

    float4 g4 = *(const float4*)(gamma + tid * 4);
    float4 b4 = *(const float4*)(beta + tid * 4);
    float4 y;
    y.x = fmaf(d.x * r, g4.x, b4.x);
    y.y = fmaf(d.y * r, g4.y, b4.y);
    y.z = fmaf(d.z * r, g4.z, b4.z);
    y.w = fmaf(d.w * r, g4.w, b4.w);
    *(float4*)(out + base) = y;
}

// ---------------------------------------------------------------------------
extern "C" void kernel_launch(void* const* d_in, const int* in_sizes, int n_in,
                              void* d_out, int out_size)
{
    const float* v_code   = (const float*)d_in[0];
    const float* obs_code = (const float*)d_in[1];
    const float* Wq       = (const float*)d_in[2];
    const float* Wk       = (const float*)d_in[3];
    const float* Wv       = (const float*)d_in[4];
    const float* gamma    = (const float*)d_in[5];
    const float* beta     = (const float*)d_in[6];
    float* out = (float*)d_out;

    __half *vch, *obh, *Wcat, *QKV, *KoVo, *VoT, *S;
    float *Opart, *Zpart;
    cudaGetSymbolAddress((void**)&vch,   g_vcode_h);
    cudaGetSymbolAddress((void**)&obh,   g_obs_h);
    cudaGetSymbolAddress((void**)&Wcat,  g_Wcat);
    cudaGetSymbolAddress((void**)&QKV,   g_QKV);
    cudaGetSymbolAddress((void**)&KoVo,  g_KoVo);
    cudaGetSymbolAddress((void**)&VoT,   g_VoT);
    cudaGetSymbolAddress((void**)&S,     g_S);
    cudaGetSymbolAddress((void**)&Opart, g_Opart);
    cudaGetSymbolAddress((void**)&Zpart, g_Zpart);

    cudaFuncSetAttribute(proj_gemm,  cudaFuncAttributeMaxDynamicSharedMemorySize, G_SMEM_TOTAL);
    cudaFuncSetAttribute(score_gemm, cudaFuncAttributeMaxDynamicSharedMemorySize, S_SMEM_TOTAL);
    cudaFuncSetAttribute(out_gemm,   cudaFuncAttributeMaxDynamicSharedMemorySize, G_SMEM_TOTAL);

    // One merged fp16 conversion launch for all 5 inputs
    cvt_all<<<(CVT_TOTAL + 255) / 256, 256>>>(v_code, obs_code, Wq, Wk, Wv,
                                              vch, obh, Wcat);

    // Merged projections: QKV (384 CTAs) + KoVo (128 CTAs)
    proj_gemm<<<512, GTHREADS, G_SMEM_TOTAL>>>(vch, obh, Wcat, QKV, KoVo);

    // VoT = Vo^T  [512, 4096]
    transpose_vo<<<dim3(MM_ / 32, EE_ / 32), 256>>>(KoVo, VoT);

    // S = exp((Q @ Ko^T)/T) unnormalized [8192, 4096] + Zpart (f16 acc, 256x256)
    score_gemm<<<dim3(MM_ / SBN, NN_ / SBM), GTHREADS, S_SMEM_TOTAL>>>(QKV, KoVo, S, Zpart);

    // O partials = expS @ VoT^T, split-K=4
    out_gemm<<<dim3(EE_ / GBN, NN_ / GBM, 4), GTHREADS, G_SMEM_TOTAL>>>(S, VoT, Opart);

    // Fused: self score + normalization + residual + LayerNorm
    ln_residual<<<NN_, 128>>>(Opart, QKV, Zpart, v_code, gamma, beta, out);
}